// round 15
// baseline (speedup 1.0000x reference)
#include <cuda_runtime.h>

#define T_TOK   32768
#define D_DIM   2048
#define NE      8
#define NGROUPS (T_TOK / 16)   // 2048 groups of 16 tokens
#define NITER   (D_DIM / 32)   // 64 inner iterations
#define NCTA    128            // 128 CTAs x 16 warps = 2048 slots = NGROUPS exactly
#define NWARPS  16
#define THREADS 512
#define SMEM_W  131072         // weights region
#define HBUF_SZ 2048           // one h stage buffer (16 tokens x 128B)

// ---- Blackwell packed f32x2 helpers ----
__device__ __forceinline__ unsigned long long dup2(float x) {
    unsigned long long r;
    asm("mov.b64 %0, {%1, %1};" : "=l"(r) : "f"(x));
    return r;
}
__device__ __forceinline__ void fma2(unsigned long long& a, unsigned long long b, unsigned long long c) {
    asm("fma.rn.f32x2 %0, %1, %2, %0;" : "+l"(a) : "l"(b), "l"(c));
}
__device__ __forceinline__ unsigned long long add2(unsigned long long a, unsigned long long b) {
    unsigned long long r;
    asm("add.rn.f32x2 %0, %1, %2;" : "=l"(r) : "l"(a), "l"(b));
    return r;
}
__device__ __forceinline__ void unpack2(unsigned long long v, float& lo, float& hi) {
    asm("mov.b64 {%0, %1}, %2;" : "=f"(lo), "=f"(hi) : "l"(v));
}
__device__ __forceinline__ void cp16(unsigned smem_dst, const void* gsrc) {
    asm volatile("cp.async.cg.shared.global [%0], [%1], 16;" :: "r"(smem_dst), "l"(gsrc));
}
__device__ __forceinline__ void cp_commit() {
    asm volatile("cp.async.commit_group;" ::: "memory");
}
__device__ __forceinline__ void cp_wait1() {
    asm volatile("cp.async.wait_group 1;" ::: "memory");
}

// Persistent kernel: grid=128 CTAs, 512 threads (16 warps) -> 2048 warp slots
// = exactly one 16-token group per warp; 16 active warps/SM = 4.0/SMSP.
// smem: [0,128K) XOR-swizzled weights ([k][Ww e0..7|Wn e0..7], ^((k>>2)&7)<<4);
//       [128K,224K) per-warp h stage buffers (3 x 2KB each, cp.async.cg).
// Lane = (trow = lane>>3: token quad 0..3, sub = lane&7: k-slice).
// Each lane accumulates T=4 tokens (acc = 32 ull = 64 regs) so 16 warps fit
// the register file; 4 warps/SMSP cover the LDS/cp scoreboard stalls that
// bounded the T=8 variant at 2 warps/SMSP.
extern "C" __global__ void __launch_bounds__(THREADS, 1)
router_kernel(const float* __restrict__ h,  const float* __restrict__ Ww,
              const float* __restrict__ bw, const float* __restrict__ Wn,
              const float* __restrict__ bn, const float* __restrict__ eps,
              float* __restrict__ out)
{
    extern __shared__ char smem_all[];
    char* swb = smem_all;                       // weights

    const int tid = threadIdx.x;

    // Fill weights into smem with swizzle.
    #pragma unroll
    for (int it = 0; it < (D_DIM * NE) / THREADS; ++it) {
        int idx = tid + it * THREADS;      // 0..16383
        int k = idx >> 3, e = idx & 7;
        unsigned sx = ((unsigned)(k >> 2) & 7u) << 4;
        unsigned offW = ((unsigned)k * 64u + (unsigned)e * 4u) ^ sx;
        unsigned offN = ((unsigned)k * 64u + 32u + (unsigned)e * 4u) ^ sx;
        *(float*)(swb + offW) = Ww[idx];
        *(float*)(swb + offN) = Wn[idx];
    }
    __syncthreads();

    const int warp = tid >> 5;
    const int lane = tid & 31;
    const int trow = lane >> 3;          // token quad 0..3
    const int sub  = lane & 7;           // k-slice 0..7
    const unsigned subx = (unsigned)sub << 4;   // weight swizzle term

    const unsigned smem_base_u32 =
        (unsigned)__cvta_generic_to_shared(smem_all);
    const unsigned hbuf0 = smem_base_u32 + SMEM_W + (unsigned)warp * (3 * HBUF_SZ);
    char* hbuf0p = smem_all + SMEM_W + warp * (3 * HBUF_SZ);

    // Exactly one group per warp: g in [0, 2048).
    const int g = warp * gridDim.x + blockIdx.x;
    {
        // Staging lane role: instr q copies chunk sub (16B) of token q*4+trow.
        const char* gst = (const char*)h
                        + ((size_t)(g * 16 + trow)) * (D_DIM * 4) + sub * 16;
        // Read role: lane reads chunk sub of tokens trow*4 + r.
        const unsigned rdbase = (unsigned)(trow * 512 + sub * 16);

        unsigned long long acc[4][8];
        #pragma unroll
        for (int r = 0; r < 4; ++r)
            #pragma unroll
            for (int e = 0; e < 8; ++e) acc[r][e] = 0ull;

        // Warmup: stage iters 0,1 into slots 0,1.
        #pragma unroll
        for (int st = 0; st < 2; ++st) {
            const unsigned dst = hbuf0 + st * HBUF_SZ + (unsigned)lane * 16;
            #pragma unroll
            for (int q = 0; q < 4; ++q)
                cp16(dst + q * 512, gst + (size_t)q * 4 * (D_DIM * 4) + st * 128);
            cp_commit();
        }

        // One pipeline step. RS_/WS_ are compile-time ring slots (period 3).
        #define STEP(I, RS_, WS_) do {                                          \
            cp_wait1();                                                         \
            if ((I) + 2 < NITER) {                                              \
                const unsigned dst = hbuf0 + (WS_) * HBUF_SZ + (unsigned)lane * 16; \
                const char* gsi = gst + (size_t)((I) + 2) * 128;                \
                _Pragma("unroll")                                               \
                for (int q = 0; q < 4; ++q)                                     \
                    cp16(dst + q * 512, gsi + (size_t)q * 4 * (D_DIM * 4));     \
            }                                                                   \
            cp_commit();                                                        \
            const char* rb = hbuf0p + (RS_) * HBUF_SZ;                          \
            float4 cc4[4];                                                      \
            _Pragma("unroll")                                                   \
            for (int r = 0; r < 4; ++r)                                         \
                cc4[r] = *(const float4*)(rb + rdbase + r * 128);               \
            const float cc[4][4] = {                                            \
                {cc4[0].x, cc4[0].y, cc4[0].z, cc4[0].w},                       \
                {cc4[1].x, cc4[1].y, cc4[1].z, cc4[1].w},                       \
                {cc4[2].x, cc4[2].y, cc4[2].z, cc4[2].w},                       \
                {cc4[3].x, cc4[3].y, cc4[3].z, cc4[3].w}                        \
            };                                                                  \
            const int kbase = (I) * 32 + sub * 4;                               \
            _Pragma("unroll")                                                   \
            for (int j = 0; j < 4; ++j) {                                       \
                const unsigned base = ((unsigned)(kbase + j) * 64u) ^ subx;     \
                ulonglong2 w01 = *(const ulonglong2*)(swb + (base ^ 0u));       \
                ulonglong2 w23 = *(const ulonglong2*)(swb + (base ^ 16u));      \
                ulonglong2 n01 = *(const ulonglong2*)(swb + (base ^ 32u));      \
                ulonglong2 n23 = *(const ulonglong2*)(swb + (base ^ 48u));      \
                _Pragma("unroll")                                               \
                for (int r = 0; r < 4; ++r) {                                   \
                    unsigned long long hh = dup2(cc[r][j]);                     \
                    fma2(acc[r][0], w01.x, hh); fma2(acc[r][1], w01.y, hh);     \
                    fma2(acc[r][2], w23.x, hh); fma2(acc[r][3], w23.y, hh);     \
                    fma2(acc[r][4], n01.x, hh); fma2(acc[r][5], n01.y, hh);     \
                    fma2(acc[r][6], n23.x, hh); fma2(acc[r][7], n23.y, hh);     \
                }                                                               \
            }                                                                   \
        } while (0)

        // 63 = 21 x 3 full ring periods, then iter 63 (rs = 63 % 3 = 0).
        for (int ib = 0; ib < NITER - 1; ib += 3) {
            STEP(ib + 0, 0, 2);
            STEP(ib + 1, 1, 0);
            STEP(ib + 2, 2, 1);
        }
        STEP(NITER - 1, 0, 2);
        #undef STEP

        // Butterfly all-reduce across the 8 sub lanes (xor 1, 2, 4).
        #pragma unroll
        for (int s = 1; s <= 4; s <<= 1) {
            #pragma unroll
            for (int r = 0; r < 4; ++r)
                #pragma unroll
                for (int e = 0; e < 8; ++e) {
                    unsigned long long o = __shfl_xor_sync(0xffffffffu, acc[r][e], s);
                    acc[r][e] = add2(acc[r][e], o);
                }
        }

        // Lanes sub<4 each finish one token: r = sub.
        if (sub < 4) {
            unsigned long long sel[8];
            #pragma unroll
            for (int r = 0; r < 4; ++r)
                if (sub == r) {
                    #pragma unroll
                    for (int e = 0; e < 8; ++e) sel[e] = acc[r][e];
                }

            const int tok = g * 16 + trow * 4 + sub;

            float lg[8], nr[8];
            unpack2(sel[0], lg[0], lg[1]); unpack2(sel[1], lg[2], lg[3]);
            unpack2(sel[2], lg[4], lg[5]); unpack2(sel[3], lg[6], lg[7]);
            unpack2(sel[4], nr[0], nr[1]); unpack2(sel[5], nr[2], nr[3]);
            unpack2(sel[6], nr[4], nr[5]); unpack2(sel[7], nr[6], nr[7]);

            float4 e0 = __ldg((const float4*)(eps + (size_t)tok * 8));
            float4 e1 = __ldg((const float4*)(eps + (size_t)tok * 8) + 1);
            float ee[8] = {e0.x, e0.y, e0.z, e0.w, e1.x, e1.y, e1.z, e1.w};

            float noisy[8];
            #pragma unroll
            for (int e = 0; e < 8; ++e) {
                float x  = nr[e] + bn[e];
                float sp = (x > 0.f) ? (x + log1pf(expf(-x))) : log1pf(expf(x));
                noisy[e] = lg[e] + bw[e] + ee[e] * sp;
            }

            // Full softmax (max-subtracted, matches jax.nn.softmax)
            float m = noisy[0];
            #pragma unroll
            for (int e = 1; e < 8; ++e) m = fmaxf(m, noisy[e]);
            float ex[8], ssum = 0.f;
            #pragma unroll
            for (int e = 0; e < 8; ++e) { ex[e] = expf(noisy[e] - m); ssum += ex[e]; }
            float inv = 1.f / ssum;

            // Top-2, first-occurrence tie-break (matches jax.lax.top_k)
            int i1 = 0; float v1 = noisy[0];
            #pragma unroll
            for (int e = 1; e < 8; ++e) if (noisy[e] > v1) { v1 = noisy[e]; i1 = e; }
            int i2 = -1; float v2 = -3.4e38f;
            #pragma unroll
            for (int e = 0; e < 8; ++e) if (e != i1 && noisy[e] > v2) { v2 = noisy[e]; i2 = e; }

            // Sparse softmax over exactly the two kept entries (others exactly 0)
            float edd = expf(v2 - v1);
            float s1  = 1.f / (1.f + edd);
            float s2  = edd * s1;

            float sp8[8];
            #pragma unroll
            for (int e = 0; e < 8; ++e)
                sp8[e] = (e == i1) ? s1 : ((e == i2) ? s2 : 0.f);

            float* outS = out + (size_t)tok * 8;
            float* outI = out + (size_t)T_TOK * 8  + (size_t)tok * 2;
            float* outF = out + (size_t)T_TOK * 10 + (size_t)tok * 8;

            ((float4*)outS)[0] = make_float4(sp8[0], sp8[1], sp8[2], sp8[3]);
            ((float4*)outS)[1] = make_float4(sp8[4], sp8[5], sp8[6], sp8[7]);
            ((float2*)outI)[0] = make_float2((float)i1, (float)i2);
            ((float4*)outF)[0] = make_float4(ex[0] * inv, ex[1] * inv, ex[2] * inv, ex[3] * inv);
            ((float4*)outF)[1] = make_float4(ex[4] * inv, ex[5] * inv, ex[6] * inv, ex[7] * inv);
        }
    }
}

extern "C" void kernel_launch(void* const* d_in, const int* in_sizes, int n_in,
                              void* d_out, int out_size)
{
    const float* h   = (const float*)d_in[0];
    const float* Ww  = (const float*)d_in[1];
    const float* bw  = (const float*)d_in[2];
    const float* Wn  = (const float*)d_in[3];
    const float* bn  = (const float*)d_in[4];
    const float* eps = (const float*)d_in[5];

    const int smem = SMEM_W + NWARPS * 3 * HBUF_SZ;   // 131072 + 98304 = 229376
    cudaFuncSetAttribute(router_kernel, cudaFuncAttributeMaxDynamicSharedMemorySize, smem);

    // 128 CTAs x 16 warps = 2048 warp slots = NGROUPS exactly:
    // every SM runs 16 fully-active warps (4.0/SMSP).
    router_kernel<<<NCTA, THREADS, smem>>>(h, Ww, bw, Wn, bn, eps, (float*)d_out);
}

// round 16
// speedup vs baseline: 1.0341x; 1.0341x over previous
#include <cuda_runtime.h>

#define T_TOK   32768
#define D_DIM   2048
#define NE      8
#define NGROUPS (T_TOK / 32)   // 1024 groups of 32 tokens
#define NITER   (D_DIM / 32)   // 64 inner iterations
#define NCTA    128            // 128 CTAs x 8 warps = 1024 slots = NGROUPS exactly
#define SMEM_W  131072         // weights region
#define HBUF_SZ 4096           // one h stage buffer (32 tokens x 128B)

// ---- Blackwell packed f32x2 helpers ----
__device__ __forceinline__ unsigned long long dup2(float x) {
    unsigned long long r;
    asm("mov.b64 %0, {%1, %1};" : "=l"(r) : "f"(x));
    return r;
}
__device__ __forceinline__ void fma2(unsigned long long& a, unsigned long long b, unsigned long long c) {
    asm("fma.rn.f32x2 %0, %1, %2, %0;" : "+l"(a) : "l"(b), "l"(c));
}
__device__ __forceinline__ unsigned long long add2(unsigned long long a, unsigned long long b) {
    unsigned long long r;
    asm("add.rn.f32x2 %0, %1, %2;" : "=l"(r) : "l"(a), "l"(b));
    return r;
}
__device__ __forceinline__ void unpack2(unsigned long long v, float& lo, float& hi) {
    asm("mov.b64 {%0, %1}, %2;" : "=f"(lo), "=f"(hi) : "l"(v));
}
__device__ __forceinline__ void cp16(unsigned smem_dst, const void* gsrc) {
    asm volatile("cp.async.cg.shared.global [%0], [%1], 16;" :: "r"(smem_dst), "l"(gsrc));
}
__device__ __forceinline__ void cp_commit() {
    asm volatile("cp.async.commit_group;" ::: "memory");
}
__device__ __forceinline__ void cp_wait1() {
    asm volatile("cp.async.wait_group 1;" ::: "memory");
}

// Persistent kernel: grid=128 CTAs (8 warps each -> 1024 warp slots, exactly
// one 32-token group per warp, 8 active warps on EVERY SM = 2.0/SMSP).
// smem: [0,128K) XOR-swizzled weights ([k][Ww e0..7|Wn e0..7], ^((k>>2)&7)<<4);
//       [128K,224K) per-warp h stage buffers (3 x 4KB each, cp.async.cg).
// Lane = (trow = lane>>3: token octet 0..3, sub = lane&7: k-slice).
// NEW (R16): the two warps sharing an SMSP are phase-SKEWED by ~half an
// iteration (odd warps nanosleep once before the loop) so one warp's
// LDS/cp-wait window overlaps the other's FMA burst instead of colliding.
extern "C" __global__ void __launch_bounds__(256, 1)
router_kernel(const float* __restrict__ h,  const float* __restrict__ Ww,
              const float* __restrict__ bw, const float* __restrict__ Wn,
              const float* __restrict__ bn, const float* __restrict__ eps,
              float* __restrict__ out)
{
    extern __shared__ char smem_all[];
    char* swb = smem_all;                       // weights

    const int tid = threadIdx.x;

    // Fill weights into smem with swizzle.
    #pragma unroll
    for (int it = 0; it < (D_DIM * NE) / 256; ++it) {
        int idx = tid + it * 256;          // 0..16383
        int k = idx >> 3, e = idx & 7;
        unsigned sx = ((unsigned)(k >> 2) & 7u) << 4;
        unsigned offW = ((unsigned)k * 64u + (unsigned)e * 4u) ^ sx;
        unsigned offN = ((unsigned)k * 64u + 32u + (unsigned)e * 4u) ^ sx;
        *(float*)(swb + offW) = Ww[idx];
        *(float*)(swb + offN) = Wn[idx];
    }
    __syncthreads();

    const int warp = tid >> 5;
    const int lane = tid & 31;
    const int trow = lane >> 3;          // token octet 0..3
    const int sub  = lane & 7;           // k-slice 0..7
    const unsigned subx = (unsigned)sub << 4;   // weight swizzle term

    // Anti-phase skew: warps (w, w+4) share an SMSP (wid % 4). Delay the
    // higher one by ~half the measured per-iter period so their FMA bursts
    // interleave with each other's LDS/cp-wait windows.
    if (warp >= 4) __nanosleep(256);

    // This warp's 3 h stage buffers (shared-space u32 addresses).
    const unsigned smem_base_u32 =
        (unsigned)__cvta_generic_to_shared(smem_all);
    const unsigned hbuf0 = smem_base_u32 + SMEM_W + (unsigned)warp * (3 * HBUF_SZ);
    char* hbuf0p = smem_all + SMEM_W + warp * (3 * HBUF_SZ);

    for (int g = warp * gridDim.x + blockIdx.x; g < NGROUPS; g += gridDim.x * 8) {
        // Staging lane role: instr q copies chunk sub (16B) of token q*4+trow.
        const char* gst = (const char*)h
                        + ((size_t)(g * 32 + trow)) * (D_DIM * 4) + sub * 16;
        // Read role: lane reads chunk sub of tokens trow*8 + r.
        const unsigned rdbase = (unsigned)(trow * 1024 + sub * 16);

        unsigned long long acc[8][8];
        #pragma unroll
        for (int r = 0; r < 8; ++r)
            #pragma unroll
            for (int e = 0; e < 8; ++e) acc[r][e] = 0ull;

        // Warmup: stage iters 0,1 into slots 0,1.
        #pragma unroll
        for (int st = 0; st < 2; ++st) {
            const unsigned dst = hbuf0 + st * HBUF_SZ + (unsigned)lane * 16;
            #pragma unroll
            for (int q = 0; q < 8; ++q)
                cp16(dst + q * 512, gst + (size_t)q * 4 * (D_DIM * 4) + st * 128);
            cp_commit();
        }

        int rs = 0;        // read slot  (i % 3)
        int ws = 2;        // write slot ((i+2) % 3)
        #pragma unroll 2
        for (int i = 0; i < NITER; ++i) {
            cp_wait1();                        // stage i complete

            // Read this iter's 32 h values (8 tokens x 4 floats) from smem.
            const char* rb = hbuf0p + rs * HBUF_SZ;
            float4 cc4[8];
            #pragma unroll
            for (int r = 0; r < 8; ++r)
                cc4[r] = *(const float4*)(rb + rdbase + r * 128);

            // Stage iter i+2 into slot ws (reads for that slot finished i-1).
            if (i + 2 < NITER) {
                const unsigned dst = hbuf0 + ws * HBUF_SZ + (unsigned)lane * 16;
                const char* gsi = gst + (size_t)(i + 2) * 128;
                #pragma unroll
                for (int q = 0; q < 8; ++q)
                    cp16(dst + q * 512, gsi + (size_t)q * 4 * (D_DIM * 4));
            }
            cp_commit();

            const float cc[8][4] = {
                {cc4[0].x, cc4[0].y, cc4[0].z, cc4[0].w},
                {cc4[1].x, cc4[1].y, cc4[1].z, cc4[1].w},
                {cc4[2].x, cc4[2].y, cc4[2].z, cc4[2].w},
                {cc4[3].x, cc4[3].y, cc4[3].z, cc4[3].w},
                {cc4[4].x, cc4[4].y, cc4[4].z, cc4[4].w},
                {cc4[5].x, cc4[5].y, cc4[5].z, cc4[5].w},
                {cc4[6].x, cc4[6].y, cc4[6].z, cc4[6].w},
                {cc4[7].x, cc4[7].y, cc4[7].z, cc4[7].w}
            };

            const int kbase = i * 32 + sub * 4;
            #pragma unroll
            for (int j = 0; j < 4; ++j) {
                const unsigned base = ((unsigned)(kbase + j) * 64u) ^ subx;
                ulonglong2 w01 = *(const ulonglong2*)(swb + (base ^ 0u));
                ulonglong2 w23 = *(const ulonglong2*)(swb + (base ^ 16u));
                ulonglong2 n01 = *(const ulonglong2*)(swb + (base ^ 32u));
                ulonglong2 n23 = *(const ulonglong2*)(swb + (base ^ 48u));
                #pragma unroll
                for (int r = 0; r < 8; ++r) {
                    unsigned long long hh = dup2(cc[r][j]);
                    fma2(acc[r][0], w01.x, hh); fma2(acc[r][1], w01.y, hh);
                    fma2(acc[r][2], w23.x, hh); fma2(acc[r][3], w23.y, hh);
                    fma2(acc[r][4], n01.x, hh); fma2(acc[r][5], n01.y, hh);
                    fma2(acc[r][6], n23.x, hh); fma2(acc[r][7], n23.y, hh);
                }
            }

            rs = (rs == 2) ? 0 : rs + 1;
            ws = (ws == 2) ? 0 : ws + 1;
        }

        // Butterfly all-reduce across the 8 sub lanes (xor 1, 2, 4).
        #pragma unroll
        for (int s = 1; s <= 4; s <<= 1) {
            #pragma unroll
            for (int r = 0; r < 8; ++r)
                #pragma unroll
                for (int e = 0; e < 8; ++e) {
                    unsigned long long o = __shfl_xor_sync(0xffffffffu, acc[r][e], s);
                    acc[r][e] = add2(acc[r][e], o);
                }
        }

        // Every lane finishes exactly one token: r = sub (0..7).
        {
            unsigned long long sel[8];
            #pragma unroll
            for (int r = 0; r < 8; ++r)
                if (sub == r) {
                    #pragma unroll
                    for (int e = 0; e < 8; ++e) sel[e] = acc[r][e];
                }

            const int tok = g * 32 + trow * 8 + sub;

            float lg[8], nr[8];
            unpack2(sel[0], lg[0], lg[1]); unpack2(sel[1], lg[2], lg[3]);
            unpack2(sel[2], lg[4], lg[5]); unpack2(sel[3], lg[6], lg[7]);
            unpack2(sel[4], nr[0], nr[1]); unpack2(sel[5], nr[2], nr[3]);
            unpack2(sel[6], nr[4], nr[5]); unpack2(sel[7], nr[6], nr[7]);

            float4 e0 = __ldg((const float4*)(eps + (size_t)tok * 8));
            float4 e1 = __ldg((const float4*)(eps + (size_t)tok * 8) + 1);
            float ee[8] = {e0.x, e0.y, e0.z, e0.w, e1.x, e1.y, e1.z, e1.w};

            float noisy[8];
            #pragma unroll
            for (int e = 0; e < 8; ++e) {
                float x  = nr[e] + bn[e];
                float sp = (x > 0.f) ? (x + log1pf(expf(-x))) : log1pf(expf(x));
                noisy[e] = lg[e] + bw[e] + ee[e] * sp;
            }

            // Full softmax (max-subtracted, matches jax.nn.softmax)
            float m = noisy[0];
            #pragma unroll
            for (int e = 1; e < 8; ++e) m = fmaxf(m, noisy[e]);
            float ex[8], ssum = 0.f;
            #pragma unroll
            for (int e = 0; e < 8; ++e) { ex[e] = expf(noisy[e] - m); ssum += ex[e]; }
            float inv = 1.f / ssum;

            // Top-2, first-occurrence tie-break (matches jax.lax.top_k)
            int i1 = 0; float v1 = noisy[0];
            #pragma unroll
            for (int e = 1; e < 8; ++e) if (noisy[e] > v1) { v1 = noisy[e]; i1 = e; }
            int i2 = -1; float v2 = -3.4e38f;
            #pragma unroll
            for (int e = 0; e < 8; ++e) if (e != i1 && noisy[e] > v2) { v2 = noisy[e]; i2 = e; }

            // Sparse softmax over exactly the two kept entries (others exactly 0)
            float edd = expf(v2 - v1);
            float s1  = 1.f / (1.f + edd);
            float s2  = edd * s1;

            float sp8[8];
            #pragma unroll
            for (int e = 0; e < 8; ++e)
                sp8[e] = (e == i1) ? s1 : ((e == i2) ? s2 : 0.f);

            float* outS = out + (size_t)tok * 8;
            float* outI = out + (size_t)T_TOK * 8  + (size_t)tok * 2;
            float* outF = out + (size_t)T_TOK * 10 + (size_t)tok * 8;

            ((float4*)outS)[0] = make_float4(sp8[0], sp8[1], sp8[2], sp8[3]);
            ((float4*)outS)[1] = make_float4(sp8[4], sp8[5], sp8[6], sp8[7]);
            ((float2*)outI)[0] = make_float2((float)i1, (float)i2);
            ((float4*)outF)[0] = make_float4(ex[0] * inv, ex[1] * inv, ex[2] * inv, ex[3] * inv);
            ((float4*)outF)[1] = make_float4(ex[4] * inv, ex[5] * inv, ex[6] * inv, ex[7] * inv);
        }
    }
}

extern "C" void kernel_launch(void* const* d_in, const int* in_sizes, int n_in,
                              void* d_out, int out_size)
{
    const float* h   = (const float*)d_in[0];
    const float* Ww  = (const float*)d_in[1];
    const float* bw  = (const float*)d_in[2];
    const float* Wn  = (const float*)d_in[3];
    const float* bn  = (const float*)d_in[4];
    const float* eps = (const float*)d_in[5];

    const int smem = SMEM_W + 8 * 3 * HBUF_SZ;   // 131072 + 98304 = 229376
    cudaFuncSetAttribute(router_kernel, cudaFuncAttributeMaxDynamicSharedMemorySize, smem);

    // 128 CTAs x 8 warps = 1024 warp slots = NGROUPS exactly:
    // every SM that gets a CTA runs 8 fully-active warps (2.0/SMSP).
    router_kernel<<<NCTA, 256, smem>>>(h, Ww, bw, Wn, bn, eps, (float*)d_out);
}